// round 16
// baseline (speedup 1.0000x reference)
#include <cuda_runtime.h>
#include <cuda_bf16.h>
#include <cuda_fp16.h>
#include <math_constants.h>

#define BB 2
#define NN 2048
#define HH 8
#define DD 64
#define FIN 512
#define HD 512
#define EPS 1e-5f
#define SCALE 0.125f
#define BIAS14 9.7040605f   // 14*ln2: e = exp(s/8)*2^-14 (exact power-of-2 scale)
#define NW (NN / 32)

// Device scratch
__device__ __half g_xh[BB * NN * FIN];                 // x in fp16
__device__ __half g_WT[HD * FIN];                      // W transposed [n][k] fp16
__device__ __half g_hh[BB * NN * HD];                  // projected features fp16 row-major
__device__ __half g_hhT[BB * HH * DD * NN];            // [b][h][d][n] fp16 (for V-phase)
__device__ __half g_S[(size_t)BB * HH * NN * NN];      // scaled exp values fp16
__device__ float g_O[BB * NN * HD];
__device__ float g_rowsum[BB * HH * NN];
__device__ unsigned g_mask[(size_t)BB * NN * NW];

__device__ __forceinline__ void mma_f16(float d[4], unsigned a0, unsigned a1,
                                        unsigned a2, unsigned a3,
                                        unsigned b0, unsigned b1) {
    asm volatile(
        "mma.sync.aligned.m16n8k16.row.col.f32.f16.f16.f32 "
        "{%0,%1,%2,%3}, {%4,%5,%6,%7}, {%8,%9}, {%0,%1,%2,%3};"
        : "+f"(d[0]), "+f"(d[1]), "+f"(d[2]), "+f"(d[3])
        : "r"(a0), "r"(a1), "r"(a2), "r"(a3), "r"(b0), "r"(b1));
}

// ---------------------------------------------------------------------------
// K0: prep — pack adj -> bitmask; x -> fp16; W -> fp16 transposed [n][k]
// grid: 4096 pack blocks + 2048 x-convert blocks + 64 W-transpose blocks
// ---------------------------------------------------------------------------
__global__ void k_prep(const float* __restrict__ x, const float* __restrict__ W,
                       const int* __restrict__ adj) {
    const int bid = blockIdx.x;
    const int t = threadIdx.x;

    if (bid < BB * NN) {
        // pack one adjacency row
        const int warp = t >> 5, lane = t & 31;
        const int* arow = adj + (size_t)bid * NN;
        #pragma unroll
        for (int j = warp; j < NW; j += 8) {
            unsigned bit = (arow[j * 32 + lane] != 0) ? 1u : 0u;
            unsigned word = __ballot_sync(0xffffffffu, bit);
            if (lane == 0) g_mask[(size_t)bid * NW + j] = word;
        }
    } else if (bid < BB * NN + 2048) {
        // convert 1024 floats of x -> fp16
        const int base = (bid - BB * NN) * 1024 + t * 4;
        float4 v = *(const float4*)&x[base];
        *(__half2*)&g_xh[base]     = __float22half2_rn(make_float2(v.x, v.y));
        *(__half2*)&g_xh[base + 2] = __float22half2_rn(make_float2(v.z, v.w));
    } else {
        // W transpose-convert: 64x64 tile
        __shared__ __half ws[64][72];
        const int tile = bid - (BB * NN + 2048);   // 0..63
        const int kt = tile >> 3, nt = tile & 7;
        #pragma unroll
        for (int i = 0; i < 4; i++) {
            int idx = t + i * 256;
            int r = idx >> 4, c4 = idx & 15;       // r = k-local, 4*c4 = n-local
            float4 w = *(const float4*)&W[(size_t)(kt * 64 + r) * HD + nt * 64 + c4 * 4];
            ws[c4 * 4 + 0][r] = __float2half_rn(w.x);
            ws[c4 * 4 + 1][r] = __float2half_rn(w.y);
            ws[c4 * 4 + 2][r] = __float2half_rn(w.z);
            ws[c4 * 4 + 3][r] = __float2half_rn(w.w);
        }
        __syncthreads();
        #pragma unroll
        for (int i = 0; i < 4; i++) {
            int idx = t + i * 256;
            int r = idx >> 4, c4 = idx & 15;       // r = n-local, 4*c4 = k-local
            __half2 p0 = *(__half2*)&ws[r][c4 * 4];
            __half2 p1 = *(__half2*)&ws[r][c4 * 4 + 2];
            __half* dst = &g_WT[(size_t)(nt * 64 + r) * FIN + kt * 64 + c4 * 4];
            *(__half2*)&dst[0] = p0;
            *(__half2*)&dst[2] = p1;
        }
    }
}

// ---------------------------------------------------------------------------
// K1: h = x @ W + b  (fp16 mma, cp.async pipelined, 128x64 tile / 256 threads)
// ---------------------------------------------------------------------------
#define PSTR 72   // smem stride
#define XTILE (128 * PSTR)            // halfs
#define WTILE (64 * PSTR)             // halfs
#define PROJ_SMEM ((2 * XTILE + 2 * WTILE) * 2)   // 55296 bytes

__global__ __launch_bounds__(256, 2) void k_proj(const float* __restrict__ bias) {
    extern __shared__ __align__(16) char smraw[];
    __half* Xh = (__half*)smraw;                          // [2][128*PSTR]
    __half* Wh = (__half*)(smraw + 2 * XTILE * 2);        // [2][64*PSTR]
    float* Stage = (float*)smraw;                         // overlay (36864 B)

    const int t = threadIdx.x;
    const int lane = t & 31;
    const int wid = t >> 5;
    const int g = lane >> 2;
    const int q = lane & 3;
    const int warp_m = (wid & 3) * 32;
    const int warp_n = (wid >> 2) * 32;
    const int row0 = blockIdx.y * 128;
    const int col0 = blockIdx.x * 64;

    const __half* Xg = g_xh + (size_t)row0 * FIN;
    const __half* Wg = g_WT + (size_t)col0 * FIN;

    // prefetch k-tile 0
    {
        #pragma unroll
        for (int i = 0; i < 4; i++) {
            int idx = t + i * 256;
            int r = idx >> 3, seg = idx & 7;
            unsigned d = (unsigned)__cvta_generic_to_shared(&Xh[r * PSTR + seg * 8]);
            asm volatile("cp.async.ca.shared.global [%0], [%1], 16;"
                         :: "r"(d), "l"(&Xg[(size_t)r * FIN + seg * 8]));
        }
        #pragma unroll
        for (int i = 0; i < 2; i++) {
            int idx = t + i * 256;
            int r = idx >> 3, seg = idx & 7;
            unsigned d = (unsigned)__cvta_generic_to_shared(&Wh[r * PSTR + seg * 8]);
            asm volatile("cp.async.ca.shared.global [%0], [%1], 16;"
                         :: "r"(d), "l"(&Wg[(size_t)r * FIN + seg * 8]));
        }
        asm volatile("cp.async.commit_group;");
    }

    float acc[2][4][4];
    #pragma unroll
    for (int i = 0; i < 2; i++)
        #pragma unroll
        for (int j = 0; j < 4; j++)
            #pragma unroll
            for (int e = 0; e < 4; e++) acc[i][j][e] = 0.f;

    for (int ks = 0; ks < 8; ks++) {
        asm volatile("cp.async.wait_group 0;");
        __syncthreads();

        if (ks < 7) {
            const int k0 = (ks + 1) * 64;
            __half* xn = Xh + ((ks + 1) & 1) * XTILE;
            __half* wn = Wh + ((ks + 1) & 1) * WTILE;
            #pragma unroll
            for (int i = 0; i < 4; i++) {
                int idx = t + i * 256;
                int r = idx >> 3, seg = idx & 7;
                unsigned d = (unsigned)__cvta_generic_to_shared(&xn[r * PSTR + seg * 8]);
                asm volatile("cp.async.ca.shared.global [%0], [%1], 16;"
                             :: "r"(d), "l"(&Xg[(size_t)r * FIN + k0 + seg * 8]));
            }
            #pragma unroll
            for (int i = 0; i < 2; i++) {
                int idx = t + i * 256;
                int r = idx >> 3, seg = idx & 7;
                unsigned d = (unsigned)__cvta_generic_to_shared(&wn[r * PSTR + seg * 8]);
                asm volatile("cp.async.ca.shared.global [%0], [%1], 16;"
                             :: "r"(d), "l"(&Wg[(size_t)r * FIN + k0 + seg * 8]));
            }
            asm volatile("cp.async.commit_group;");
        }

        const __half* Xc = Xh + (ks & 1) * XTILE;
        const __half* Wc = Wh + (ks & 1) * WTILE;

        #pragma unroll
        for (int kc = 0; kc < 4; kc++) {
            unsigned a[2][4];
            #pragma unroll
            for (int i = 0; i < 2; i++) {
                const __half* ar = &Xc[(warp_m + 16 * i + g) * PSTR + kc * 16];
                a[i][0] = *(const unsigned*)&ar[2 * q];
                a[i][1] = *(const unsigned*)&ar[PSTR * 8 + 2 * q];
                a[i][2] = *(const unsigned*)&ar[8 + 2 * q];
                a[i][3] = *(const unsigned*)&ar[PSTR * 8 + 8 + 2 * q];
            }
            #pragma unroll
            for (int j = 0; j < 4; j++) {
                const unsigned* br = (const unsigned*)&Wc[(warp_n + 8 * j + g) * PSTR + kc * 16];
                unsigned b0 = br[q];
                unsigned b1 = br[4 + q];
                #pragma unroll
                for (int i = 0; i < 2; i++)
                    mma_f16(acc[i][j], a[i][0], a[i][1], a[i][2], a[i][3], b0, b1);
            }
        }
        __syncthreads();
    }

    // stage fp32 result (overlays Xh — all tile reads done)
    #pragma unroll
    for (int i = 0; i < 2; i++)
        #pragma unroll
        for (int j = 0; j < 4; j++) {
            float* sr = &Stage[(warp_m + 16 * i + g) * PSTR + warp_n + 8 * j + 2 * q];
            sr[0] = acc[i][j][0];
            sr[1] = acc[i][j][1];
            sr[PSTR * 8] = acc[i][j][2];
            sr[PSTR * 8 + 1] = acc[i][j][3];
        }
    __syncthreads();

    // bias + fp16 row-major write
    #pragma unroll
    for (int i = 0; i < 8; i++) {
        int idx = t + i * 256;
        int r = idx >> 4, c4 = idx & 15;
        float4 v = *(float4*)&Stage[r * PSTR + c4 * 4];
        float4 bb = *(const float4*)&bias[col0 + c4 * 4];
        v.x += bb.x; v.y += bb.y; v.z += bb.z; v.w += bb.w;
        *(float4*)&Stage[r * PSTR + c4 * 4] = v;
        __half2 p0 = __float22half2_rn(make_float2(v.x, v.y));
        __half2 p1 = __float22half2_rn(make_float2(v.z, v.w));
        *(__half2*)&g_hh[(size_t)(row0 + r) * HD + col0 + c4 * 4] = p0;
        *(__half2*)&g_hh[(size_t)(row0 + r) * HD + col0 + c4 * 4 + 2] = p1;
    }
    __syncthreads();

    // transposed fp16 write: g_hhT[b][hh][d][n]
    const int b = row0 >> 11;
    const int n0 = row0 & (NN - 1);
    const int hh = col0 >> 6;
    #pragma unroll
    for (int i = 0; i < 8; i++) {
        int idx = t + i * 256;
        int dr = idx >> 5, nc = idx & 31;
        __half2 p0 = __float22half2_rn(make_float2(Stage[(nc * 4 + 0) * PSTR + dr],
                                                   Stage[(nc * 4 + 1) * PSTR + dr]));
        __half2 p1 = __float22half2_rn(make_float2(Stage[(nc * 4 + 2) * PSTR + dr],
                                                   Stage[(nc * 4 + 3) * PSTR + dr]));
        __half* dst = &g_hhT[((size_t)(b * HH + hh) * DD + dr) * NN + n0 + nc * 4];
        *(__half2*)&dst[0] = p0;
        *(__half2*)&dst[2] = p1;
    }
}

// ---------------------------------------------------------------------------
// K2: fused attention (mma.m16n8k16 fp16, fp32 accum), software-pipelined
// ---------------------------------------------------------------------------
#define STRH 72
#define TILEH (64 * STRH)
#define SLOTH (2 * TILEH)
#define FSMEM (3 * SLOTH * 2)

__global__ __launch_bounds__(256, 2) void k_fused() {
    extern __shared__ __half sm[];

    const int t = threadIdx.x;
    const int lane = t & 31;
    const int wid = t >> 5;
    const int g = lane >> 2;
    const int q = lane & 3;
    const int row0 = blockIdx.x * 128;
    const int bh = blockIdx.y;
    const int b = bh >> 3, hh = bh & 7;

    const __half* Hb = g_hh + (size_t)b * NN * HD + hh * DD;
    const __half* HTb = g_hhT + (size_t)bh * DD * NN;
    const int r_lo = row0 + wid * 16 + g;
    const int r_hi = r_lo + 8;

    #pragma unroll
    for (int tile = 0; tile < 2; tile++) {
        __half* kb = sm + tile * SLOTH;
        __half* vb = kb + TILEH;
        #pragma unroll
        for (int k = 0; k < 2; k++) {
            int c = t + k * 256;
            int r = c >> 3, seg = c & 7;
            unsigned dk = (unsigned)__cvta_generic_to_shared(&kb[r * STRH + seg * 8]);
            asm volatile("cp.async.ca.shared.global [%0], [%1], 16;"
                         :: "r"(dk), "l"(&Hb[(size_t)(tile * 64 + r) * HD + seg * 8]));
            unsigned dv = (unsigned)__cvta_generic_to_shared(&vb[r * STRH + seg * 8]);
            asm volatile("cp.async.ca.shared.global [%0], [%1], 16;"
                         :: "r"(dv), "l"(&HTb[(size_t)r * NN + tile * 64 + seg * 8]));
        }
        asm volatile("cp.async.commit_group;");
    }

    unsigned Qa[4][4];
    #pragma unroll
    for (int kc = 0; kc < 4; kc++) {
        Qa[kc][0] = *(const unsigned*)&Hb[(size_t)r_lo * HD + 16 * kc + 2 * q];
        Qa[kc][1] = *(const unsigned*)&Hb[(size_t)r_hi * HD + 16 * kc + 2 * q];
        Qa[kc][2] = *(const unsigned*)&Hb[(size_t)r_lo * HD + 16 * kc + 8 + 2 * q];
        Qa[kc][3] = *(const unsigned*)&Hb[(size_t)r_hi * HD + 16 * kc + 8 + 2 * q];
    }

    float Oa[8][4];
    #pragma unroll
    for (int f = 0; f < 8; f++)
        #pragma unroll
        for (int e = 0; e < 4; e++) Oa[f][e] = 0.f;
    float rs_lo = 0.f, rs_hi = 0.f;

    const unsigned* mrow_lo = &g_mask[((size_t)b * NN + r_lo) * NW];
    const unsigned* mrow_hi = &g_mask[((size_t)b * NN + r_hi) * NW];
    __half* Srow_lo = &g_S[((size_t)bh * NN + r_lo) * NN];
    __half* Srow_hi = &g_S[((size_t)bh * NN + r_hi) * NN];

    asm volatile("cp.async.wait_group 1;");
    __syncthreads();

    float Sa[8][4];
    #pragma unroll
    for (int f = 0; f < 8; f++)
        #pragma unroll
        for (int e = 0; e < 4; e++) Sa[f][e] = 0.f;
    {
        const __half* Kb = sm;
        #pragma unroll
        for (int f = 0; f < 8; f++) {
            const unsigned* kr = (const unsigned*)&Kb[(8 * f + g) * STRH];
            #pragma unroll
            for (int kc = 0; kc < 4; kc++)
                mma_f16(Sa[f], Qa[kc][0], Qa[kc][1], Qa[kc][2], Qa[kc][3],
                        kr[8 * kc + q], kr[8 * kc + 4 + q]);
        }
    }

    for (int it = 0; it < 32; it++) {
        const int m0 = it * 64;

        const unsigned m00 = __ldg(&mrow_lo[it * 2]);
        const unsigned m01 = __ldg(&mrow_lo[it * 2 + 1]);
        const unsigned m10 = __ldg(&mrow_hi[it * 2]);
        const unsigned m11 = __ldg(&mrow_hi[it * 2 + 1]);

        unsigned H01[8], H23[8];
        #pragma unroll
        for (int f = 0; f < 8; f++) {
            const unsigned wlo = (f < 4) ? m00 : m01;
            const unsigned whi = (f < 4) ? m10 : m11;
            const int sh = (8 * f + 2 * q) & 31;
            float e0 = ((wlo >> sh) & 1u)       ? __expf(fmaf(Sa[f][0], SCALE, -BIAS14)) : 0.f;
            float e1 = ((wlo >> (sh + 1)) & 1u) ? __expf(fmaf(Sa[f][1], SCALE, -BIAS14)) : 0.f;
            float e2 = ((whi >> sh) & 1u)       ? __expf(fmaf(Sa[f][2], SCALE, -BIAS14)) : 0.f;
            float e3 = ((whi >> (sh + 1)) & 1u) ? __expf(fmaf(Sa[f][3], SCALE, -BIAS14)) : 0.f;
            rs_lo += e0 + e1;
            rs_hi += e2 + e3;
            __half2 p01 = __float22half2_rn(make_float2(e0, e1));
            __half2 p23 = __float22half2_rn(make_float2(e2, e3));
            H01[f] = *(unsigned*)&p01;
            H23[f] = *(unsigned*)&p23;
            __stcs((__half2*)&Srow_lo[m0 + 8 * f + 2 * q], p01);
            __stcs((__half2*)&Srow_hi[m0 + 8 * f + 2 * q], p23);
        }

        if (it < 31) {
            __syncthreads();

            if (it < 30) {
                const int tile = it + 2;
                __half* kb = sm + (tile % 3) * SLOTH;
                __half* vb = kb + TILEH;
                #pragma unroll
                for (int k = 0; k < 2; k++) {
                    int c = t + k * 256;
                    int r = c >> 3, seg = c & 7;
                    unsigned dk = (unsigned)__cvta_generic_to_shared(&kb[r * STRH + seg * 8]);
                    asm volatile("cp.async.ca.shared.global [%0], [%1], 16;"
                                 :: "r"(dk), "l"(&Hb[(size_t)(tile * 64 + r) * HD + seg * 8]));
                    unsigned dv = (unsigned)__cvta_generic_to_shared(&vb[r * STRH + seg * 8]);
                    asm volatile("cp.async.ca.shared.global [%0], [%1], 16;"
                                 :: "r"(dv), "l"(&HTb[(size_t)r * NN + tile * 64 + seg * 8]));
                }
                asm volatile("cp.async.commit_group;");
                asm volatile("cp.async.wait_group 1;");
            } else {
                asm volatile("cp.async.wait_group 0;");
            }

            const __half* Kb = sm + ((it + 1) % 3) * SLOTH;
            #pragma unroll
            for (int f = 0; f < 8; f++)
                #pragma unroll
                for (int e = 0; e < 4; e++) Sa[f][e] = 0.f;
            #pragma unroll
            for (int f = 0; f < 8; f++) {
                const unsigned* kr = (const unsigned*)&Kb[(8 * f + g) * STRH];
                #pragma unroll
                for (int kc = 0; kc < 4; kc++)
                    mma_f16(Sa[f], Qa[kc][0], Qa[kc][1], Qa[kc][2], Qa[kc][3],
                            kr[8 * kc + q], kr[8 * kc + 4 + q]);
            }
        }

        const __half* Vb = sm + (it % 3) * SLOTH + TILEH;
        #pragma unroll
        for (int df = 0; df < 8; df++) {
            const unsigned* vr = (const unsigned*)&Vb[(8 * df + g) * STRH];
            #pragma unroll
            for (int kk = 0; kk < 4; kk++)
                mma_f16(Oa[df], H01[2 * kk], H23[2 * kk], H01[2 * kk + 1], H23[2 * kk + 1],
                        vr[8 * kk + q], vr[8 * kk + 4 + q]);
        }
    }

    // epilogue
    rs_lo += __shfl_xor_sync(0xffffffffu, rs_lo, 1);
    rs_lo += __shfl_xor_sync(0xffffffffu, rs_lo, 2);
    rs_hi += __shfl_xor_sync(0xffffffffu, rs_hi, 1);
    rs_hi += __shfl_xor_sync(0xffffffffu, rs_hi, 2);
    if (q == 0) {
        g_rowsum[(size_t)bh * NN + r_lo] = rs_lo;
        g_rowsum[(size_t)bh * NN + r_hi] = rs_hi;
    }
    const float inv_lo = 1.f / rs_lo;
    const float inv_hi = 1.f / rs_hi;
    float* O_lo = &g_O[((size_t)b * NN + r_lo) * HD + hh * DD];
    float* O_hi = &g_O[((size_t)b * NN + r_hi) * HD + hh * DD];
    #pragma unroll
    for (int df = 0; df < 8; df++) {
        *(float2*)&O_lo[8 * df + 2 * q] = make_float2(Oa[df][0] * inv_lo, Oa[df][1] * inv_lo);
        *(float2*)&O_hi[8 * df + 2 * q] = make_float2(Oa[df][2] * inv_hi, Oa[df][3] * inv_hi);
    }
}

// ---------------------------------------------------------------------------
// K3: LayerNorm (out head) + mean over heads (out tail), one block per row
// ---------------------------------------------------------------------------
__global__ void k_epi(const float* __restrict__ gamma, const float* __restrict__ beta,
                      float* __restrict__ out, float* __restrict__ out_mean) {
    __shared__ float red[256];
    __shared__ float red2[256];
    __shared__ float inv[HH];

    const int row = blockIdx.x;
    const int b = row >> 11;
    const int n = row & (NN - 1);
    const int t = threadIdx.x;

    if (t < HH) inv[t] = 0.125f / g_rowsum[(size_t)(b * HH + t) * NN + n];

    const float* v = g_O + (size_t)row * HD;
    float v0 = v[t], v1 = v[t + 256];
    red[t] = v0 + v1;
    red2[t] = v0 * v0 + v1 * v1;
    __syncthreads();
    for (int st = 128; st > 0; st >>= 1) {
        if (t < st) { red[t] += red[t + st]; red2[t] += red2[t + st]; }
        __syncthreads();
    }
    const float mu = red[0] * (1.f / HD);
    const float var = red2[0] * (1.f / HD) - mu * mu;
    const float rstd = rsqrtf(var + EPS);

    float* orow = out + (size_t)row * HD;
    orow[t] = (v0 - mu) * rstd * gamma[t] + beta[t];
    orow[t + 256] = (v1 - mu) * rstd * gamma[t + 256] + beta[t + 256];

    float acc[8];
    #pragma unroll
    for (int i = 0; i < 8; i++) acc[i] = 0.f;

    #pragma unroll
    for (int h = 0; h < HH; h++) {
        const float4 raw = __ldcs((const float4*)&g_S[((size_t)(b * HH + h) * NN + n) * NN + t * 8]);
        const __half2* hp = (const __half2*)&raw;
        const float iv = inv[h];
        #pragma unroll
        for (int j = 0; j < 4; j++) {
            float2 p = __half22float2(hp[j]);
            acc[2 * j]     += p.x * iv;
            acc[2 * j + 1] += p.y * iv;
        }
    }

    float* mrow = out_mean + (size_t)row * NN + t * 8;
    *(float4*)&mrow[0] = make_float4(acc[0], acc[1], acc[2], acc[3]);
    *(float4*)&mrow[4] = make_float4(acc[4], acc[5], acc[6], acc[7]);
}

// ---------------------------------------------------------------------------
extern "C" void kernel_launch(void* const* d_in, const int* in_sizes, int n_in,
                              void* d_out, int out_size) {
    const float* x     = (const float*)d_in[0];
    const int*   adj   = (const int*)d_in[1];
    const float* W_w   = (const float*)d_in[2];
    const float* W_b   = (const float*)d_in[3];
    const float* gamma = (const float*)d_in[4];
    const float* beta  = (const float*)d_in[5];
    float* out = (float*)d_out;
    float* out_mean = out + (size_t)BB * NN * HD;

    cudaFuncSetAttribute(k_proj, cudaFuncAttributeMaxDynamicSharedMemorySize, PROJ_SMEM);
    cudaFuncSetAttribute(k_fused, cudaFuncAttributeMaxDynamicSharedMemorySize, FSMEM);

    k_prep<<<BB * NN + 2048 + 64, 256>>>(x, W_w, adj);
    k_proj<<<dim3(HD / 64, (BB * NN) / 128), 256, PROJ_SMEM>>>(W_b);
    k_fused<<<dim3(NN / 128, BB * HH), 256, FSMEM>>>();
    k_epi<<<BB * NN, 256>>>(gamma, beta, out, out_mean);
}